// round 2
// baseline (speedup 1.0000x reference)
#include <cuda_runtime.h>
#include <cuda_bf16.h>

// Problem dims (fixed by the dataset)
#define NMAX   50000
#define EMAX   800000
#define ETMAX  (NMAX + EMAX)      // edges + self loops
#define F1     128                // input features
#define H1     4                  // layer-1 heads
#define C1     32                 // layer-1 channels/head
#define D1     (H1 * C1)          // 128
#define D2     64                 // layer-2 out channels (1 head)
#define NEG_SLOPE 0.2f

// ---------------- scratch (static device globals; no allocation) -----------
static __device__ float g_h1  [NMAX * D1];   // x @ W1
static __device__ float g_out1[NMAX * D1];   // layer-1 aggregated output (then ELU)
static __device__ float g_h2  [NMAX * D2];   // elu(out1) @ W2
static __device__ float g_as1 [NMAX * H1];
static __device__ float g_ad1 [NMAX * H1];
static __device__ float g_m1  [NMAX * H1];
static __device__ float g_den1[NMAX * H1];
static __device__ float g_as2 [NMAX];
static __device__ float g_ad2 [NMAX];
static __device__ float g_m2  [NMAX];
static __device__ float g_den2[NMAX];
static __device__ int   g_src [ETMAX];
static __device__ int   g_dst [ETMAX];
static __device__ int   g_flag[1];           // 1 => edge_index is int32, 0 => int64

// ---------------- helpers --------------------------------------------------
__device__ __forceinline__ void atomicMaxFloat(float* addr, float val) {
    if (val >= 0.0f) atomicMax((int*)addr, __float_as_int(val));
    else             atomicMin((unsigned int*)addr, __float_as_uint(val));
}

__device__ __forceinline__ void red_add_v4(float* p, float4 v) {
    asm volatile("red.global.add.v4.f32 [%0], {%1,%2,%3,%4};"
                 :: "l"(p), "f"(v.x), "f"(v.y), "f"(v.z), "f"(v.w) : "memory");
}

__device__ __forceinline__ float lrelu(float v) {
    return v > 0.0f ? v : NEG_SLOPE * v;
}

// ---------------- dtype detection + edge conversion ------------------------
__global__ void k_detect(const void* ei, int E, int N) {
    if (threadIdx.x == 0) g_flag[0] = 0;
    __syncthreads();
    const long long* p = (const long long*)ei;
    int S = 2048;                       // 16KB read: in-bounds under both dtypes
    int bad = 0;
    for (int i = threadIdx.x; i < S; i += blockDim.x) {
        long long v = p[i];
        if (v < 0 || v >= (long long)N) bad = 1;
    }
    if (bad) atomicOr(&g_flag[0], 1);   // i64 interp invalid => data is int32
}

__global__ void k_convert(const void* ei, int E, int Etot, int N) {
    int i = blockIdx.x * blockDim.x + threadIdx.x;
    if (i >= Etot) return;
    int s, d;
    if (i < E) {
        if (g_flag[0]) {
            const int* p = (const int*)ei;
            s = p[i]; d = p[E + i];
        } else {
            const long long* p = (const long long*)ei;
            s = (int)p[i]; d = (int)p[E + i];
        }
    } else {
        s = d = i - E;                  // self loops
    }
    // defensive clamp: a misdetected dtype becomes a numeric error, never OOB
    s = min(max(s, 0), N - 1);
    d = min(max(d, 0), N - 1);
    g_src[i] = s;
    g_dst[i] = d;
}

// ---------------- tiny GEMM: C[N,KOUT] = A[N,K] * B[K,KOUT] ----------------
// blockDim = KOUT; each block computes R rows; A rows staged in shared,
// B stays hot in L1 (<=64 KB).
template<int K, int KOUT, int R>
__global__ void k_gemm(const float* __restrict__ A, const float* __restrict__ B,
                       float* __restrict__ C, int Nrows) {
    __shared__ float sA[R][K];
    int row0 = blockIdx.x * R;
    int col  = threadIdx.x;
    for (int i = threadIdx.x; i < R * K; i += KOUT) {
        int r = i / K, k = i - r * K;
        sA[r][k] = (row0 + r < Nrows) ? A[(row0 + r) * K + k] : 0.0f;
    }
    __syncthreads();
    float acc[R];
    #pragma unroll
    for (int r = 0; r < R; r++) acc[r] = 0.0f;
    #pragma unroll 4
    for (int k = 0; k < K; k++) {
        float b = __ldg(&B[k * KOUT + col]);
        #pragma unroll
        for (int r = 0; r < R; r++) acc[r] += sA[r][k] * b;
    }
    #pragma unroll
    for (int r = 0; r < R; r++)
        if (row0 + r < Nrows) C[(row0 + r) * KOUT + col] = acc[r];
}

// ---------------- per-node attention logits --------------------------------
template<int H, int C>
__global__ void k_att(const float* __restrict__ Hm,
                      const float* __restrict__ att_s, const float* __restrict__ att_d,
                      float* __restrict__ as_, float* __restrict__ ad_, int N) {
    int idx = blockIdx.x * blockDim.x + threadIdx.x;
    if (idx >= N * H) return;
    int n = idx / H, h = idx - n * H;
    const float* hp = Hm + n * (H * C) + h * C;
    float ss = 0.0f, ds = 0.0f;
    #pragma unroll 8
    for (int c = 0; c < C; c++) {
        float v = hp[c];
        ss += v * __ldg(&att_s[h * C + c]);
        ds += v * __ldg(&att_d[h * C + c]);
    }
    as_[idx] = ss;
    ad_[idx] = ds;
}

// ---------------- fused softmax-state init ---------------------------------
// m <- -inf (nm elems), den <- 0 (nm elems), out <- 0 (nout elems)
__global__ void k_init(float* __restrict__ m, float* __restrict__ den, int nm,
                       float* __restrict__ outbuf, int nout) {
    int i = blockIdx.x * blockDim.x + threadIdx.x;
    if (i < nm) { m[i] = -INFINITY; den[i] = 0.0f; }
    for (int j = i; j < nout; j += gridDim.x * blockDim.x) outbuf[j] = 0.0f;
}

// ---------------- edge softmax passes --------------------------------------
template<int H>
__global__ void k_edge_max(const float* __restrict__ as_, const float* __restrict__ ad_,
                           float* __restrict__ m, int Etot) {
    int i = blockIdx.x * blockDim.x + threadIdx.x;
    if (i >= Etot * H) return;
    int e = i / H, h = i - e * H;
    int s = g_src[e], d = g_dst[e];
    float v = lrelu(as_[s * H + h] + ad_[d * H + h]);
    atomicMaxFloat(&m[d * H + h], v);
}

template<int H>
__global__ void k_edge_sum(const float* __restrict__ as_, const float* __restrict__ ad_,
                           const float* __restrict__ m, float* __restrict__ den, int Etot) {
    int i = blockIdx.x * blockDim.x + threadIdx.x;
    if (i >= Etot * H) return;
    int e = i / H, h = i - e * H;
    int s = g_src[e], d = g_dst[e];
    float v = lrelu(as_[s * H + h] + ad_[d * H + h]);
    atomicAdd(&den[d * H + h], __expf(v - m[d * H + h]));
}

// ---------------- aggregation: out[dst] += h[src] * alpha ------------------
// G = D/4 lanes per edge; each lane does one float4 of channels.
template<int H, int C>
__global__ void k_edge_agg(const float* __restrict__ Hm,
                           const float* __restrict__ as_, const float* __restrict__ ad_,
                           const float* __restrict__ m, const float* __restrict__ den,
                           float* __restrict__ out, int Etot) {
    constexpr int D = H * C;
    constexpr int G = D / 4;
    int t = blockIdx.x * blockDim.x + threadIdx.x;
    int e = t / G;
    if (e >= Etot) return;
    int g  = t - e * G;
    int ch = g * 4;
    int h  = ch / C;
    int s = g_src[e], d = g_dst[e];
    float v = lrelu(as_[s * H + h] + ad_[d * H + h]);
    float alpha = __expf(v - m[d * H + h]) / den[d * H + h];
    float4 hv = *(const float4*)(Hm + s * D + ch);
    float4 o;
    o.x = hv.x * alpha; o.y = hv.y * alpha; o.z = hv.z * alpha; o.w = hv.w * alpha;
    red_add_v4(out + d * D + ch, o);
}

// ---------------- epilogues ------------------------------------------------
__global__ void k_bias_elu(float* __restrict__ p, const float* __restrict__ b, int N) {
    int i = blockIdx.x * blockDim.x + threadIdx.x;
    if (i >= N * D1) return;
    float v = p[i] + __ldg(&b[i & (D1 - 1)]);
    p[i] = v > 0.0f ? v : expm1f(v);
}

__global__ void k_bias_add(float* __restrict__ p, const float* __restrict__ b, int N) {
    int i = blockIdx.x * blockDim.x + threadIdx.x;
    if (i >= N * D2) return;
    p[i] += __ldg(&b[i & (D2 - 1)]);
}

// ---------------- launcher -------------------------------------------------
static inline unsigned cdiv(long long a, long long b) { return (unsigned)((a + b - 1) / b); }

extern "C" void kernel_launch(void* const* d_in, const int* in_sizes, int n_in,
                              void* d_out, int out_size) {
    const float* x        = (const float*)d_in[0];
    const void*  ei       = d_in[1];
    const float* W1       = (const float*)d_in[2];
    const float* att_src1 = (const float*)d_in[3];
    const float* att_dst1 = (const float*)d_in[4];
    const float* b1       = (const float*)d_in[5];
    const float* W2       = (const float*)d_in[6];
    const float* att_src2 = (const float*)d_in[7];
    const float* att_dst2 = (const float*)d_in[8];
    const float* b2       = (const float*)d_in[9];
    float* out            = (float*)d_out;

    const int N    = in_sizes[0] / F1;
    const int E    = in_sizes[1] / 2;
    const int Etot = E + N;

    float *h1, *out1, *h2, *as1, *ad1, *m1, *den1, *as2, *ad2, *m2, *den2;
    cudaGetSymbolAddress((void**)&h1,   g_h1);
    cudaGetSymbolAddress((void**)&out1, g_out1);
    cudaGetSymbolAddress((void**)&h2,   g_h2);
    cudaGetSymbolAddress((void**)&as1,  g_as1);
    cudaGetSymbolAddress((void**)&ad1,  g_ad1);
    cudaGetSymbolAddress((void**)&m1,   g_m1);
    cudaGetSymbolAddress((void**)&den1, g_den1);
    cudaGetSymbolAddress((void**)&as2,  g_as2);
    cudaGetSymbolAddress((void**)&ad2,  g_ad2);
    cudaGetSymbolAddress((void**)&m2,   g_m2);
    cudaGetSymbolAddress((void**)&den2, g_den2);

    // edges: dtype-detect, convert to int32 SoA, append self loops
    k_detect<<<1, 256>>>(ei, E, N);
    k_convert<<<cdiv(Etot, 256), 256>>>(ei, E, Etot, N);

    // ---- layer 1 ----
    k_gemm<F1, D1, 4><<<cdiv(N, 4), D1>>>(x, W1, h1, N);
    k_att<H1, C1><<<cdiv((long long)N * H1, 256), 256>>>(h1, att_src1, att_dst1, as1, ad1, N);

    k_init<<<cdiv((long long)N * H1, 256), 256>>>(m1, den1, N * H1, out1, N * D1);

    k_edge_max<H1><<<cdiv((long long)Etot * H1, 256), 256>>>(as1, ad1, m1, Etot);
    k_edge_sum<H1><<<cdiv((long long)Etot * H1, 256), 256>>>(as1, ad1, m1, den1, Etot);
    k_edge_agg<H1, C1><<<cdiv((long long)Etot * (D1 / 4), 256), 256>>>(h1, as1, ad1, m1, den1, out1, Etot);

    k_bias_elu<<<cdiv((long long)N * D1, 256), 256>>>(out1, b1, N);

    // ---- layer 2 ----
    k_gemm<D1, D2, 4><<<cdiv(N, 4), D2>>>(out1, W2, h2, N);
    k_att<1, D2><<<cdiv(N, 256), 256>>>(h2, att_src2, att_dst2, as2, ad2, N);

    k_init<<<cdiv(N, 256), 256>>>(m2, den2, N, out, N * D2);

    k_edge_max<1><<<cdiv(Etot, 256), 256>>>(as2, ad2, m2, Etot);
    k_edge_sum<1><<<cdiv(Etot, 256), 256>>>(as2, ad2, m2, den2, Etot);
    k_edge_agg<1, D2><<<cdiv((long long)Etot * (D2 / 4), 256), 256>>>(h2, as2, ad2, m2, den2, out, Etot);

    k_bias_add<<<cdiv((long long)N * D2, 256), 256>>>(out, b2, N);
}

// round 3
// speedup vs baseline: 1.1732x; 1.1732x over previous
#include <cuda_runtime.h>
#include <cuda_bf16.h>

// Problem dims (fixed by the dataset)
#define NMAX   50000
#define EMAX   800000
#define ETMAX  (NMAX + EMAX)      // edges + self loops
#define F1     128                // input features
#define H1     4                  // layer-1 heads
#define C1     32                 // layer-1 channels/head
#define D1     (H1 * C1)          // 128
#define D2     64                 // layer-2 out channels (1 head)
#define NEG_SLOPE 0.2f

// ---------------- scratch (static device globals; no allocation) -----------
static __device__ float g_h1  [NMAX * D1];    // x @ W1
static __device__ float g_out1[NMAX * D1];    // layer-1 aggregated (bias baked in)
static __device__ float g_h2  [NMAX * D2];    // elu(out1) @ W2
static __device__ float g_as1 [NMAX * H1];
static __device__ float g_ad1 [NMAX * H1];
static __device__ float g_m1  [NMAX * H1];
static __device__ float g_den1[NMAX * H1];
static __device__ float g_as2 [NMAX];
static __device__ float g_ad2 [NMAX];
static __device__ float g_m2  [NMAX];
static __device__ float g_den2[NMAX];
static __device__ float g_e   [ETMAX * H1];   // per-edge logits, then reused per layer
static __device__ float g_p   [ETMAX * H1];   // exp(e - m[dst]); becomes alpha
static __device__ int2  g_sd  [ETMAX];        // (src, dst) pairs
static __device__ int   g_flag[1];            // 1 => edge_index is int32, 0 => int64

// ---------------- helpers --------------------------------------------------
__device__ __forceinline__ void atomicMaxFloat(float* addr, float val) {
    if (val >= 0.0f) atomicMax((int*)addr, __float_as_int(val));
    else             atomicMin((unsigned int*)addr, __float_as_uint(val));
}

__device__ __forceinline__ void red_add_v4(float* p, float4 v) {
    asm volatile("red.global.add.v4.f32 [%0], {%1,%2,%3,%4};"
                 :: "l"(p), "f"(v.x), "f"(v.y), "f"(v.z), "f"(v.w) : "memory");
}

__device__ __forceinline__ float lrelu(float v) {
    return v > 0.0f ? v : NEG_SLOPE * v;
}

__device__ __forceinline__ float warp_sum(float v) {
    #pragma unroll
    for (int o = 16; o > 0; o >>= 1) v += __shfl_xor_sync(0xFFFFFFFFu, v, o);
    return v;
}

// ---------------- dtype detection + edge conversion ------------------------
__global__ void k_detect(const void* ei, int E, int N) {
    if (threadIdx.x == 0) g_flag[0] = 0;
    __syncthreads();
    const long long* p = (const long long*)ei;
    int S = 2048;                       // 16KB read: in-bounds under both dtypes
    int bad = 0;
    for (int i = threadIdx.x; i < S; i += blockDim.x) {
        long long v = p[i];
        if (v < 0 || v >= (long long)N) bad = 1;
    }
    if (bad) atomicOr(&g_flag[0], 1);   // i64 interp invalid => data is int32
}

__global__ void k_convert(const void* ei, int E, int Etot, int N) {
    int i = blockIdx.x * blockDim.x + threadIdx.x;
    if (i >= Etot) return;
    int s, d;
    if (i < E) {
        if (g_flag[0]) {
            const int* p = (const int*)ei;
            s = p[i]; d = p[E + i];
        } else {
            const long long* p = (const long long*)ei;
            s = (int)p[i]; d = (int)p[E + i];
        }
    } else {
        s = d = i - E;                  // self loops
    }
    s = min(max(s, 0), N - 1);          // misdetect => numeric error, never OOB
    d = min(max(d, 0), N - 1);
    g_sd[i] = make_int2(s, d);
}

// ------- GEMM fused with attention logits (and optional ELU on A load) -----
// C[N,KOUT] = act(A)[N,K] * B[K,KOUT];  as/ad[n,h] = sum_c C[n,h*CH+c]*att[h*CH+c]
// blockDim = KOUT threads; R rows per block. B stays hot in L1.
template<int K, int KOUT, int H, int R, bool ELU_IN>
__global__ void k_gemm_att(const float* __restrict__ A, const float* __restrict__ B,
                           float* __restrict__ C,
                           const float* __restrict__ att_s_w, const float* __restrict__ att_d_w,
                           float* __restrict__ as_, float* __restrict__ ad_, int Nrows) {
    constexpr int NW = KOUT / 32;          // warps per block
    __shared__ float sA[R][K];
    __shared__ float sred[NW][R][2];
    int row0 = blockIdx.x * R;
    int col  = threadIdx.x;
    int w    = col >> 5, lane = col & 31;

    for (int i = threadIdx.x; i < R * K; i += KOUT) {
        int r = i / K, k = i - r * K;
        float v = (row0 + r < Nrows) ? A[(row0 + r) * K + k] : 0.0f;
        if (ELU_IN) v = v > 0.0f ? v : expm1f(v);
        sA[r][k] = v;
    }
    __syncthreads();

    float acc[R];
    #pragma unroll
    for (int r = 0; r < R; r++) acc[r] = 0.0f;
    #pragma unroll 4
    for (int k = 0; k < K; k++) {
        float b = __ldg(&B[k * KOUT + col]);
        #pragma unroll
        for (int r = 0; r < R; r++) acc[r] += sA[r][k] * b;
    }

    float aw_s = __ldg(&att_s_w[col]);
    float aw_d = __ldg(&att_d_w[col]);
    #pragma unroll
    for (int r = 0; r < R; r++) {
        if (row0 + r < Nrows) C[(row0 + r) * KOUT + col] = acc[r];
        float ps = warp_sum(acc[r] * aw_s);
        float pd = warp_sum(acc[r] * aw_d);
        if (lane == 0) { sred[w][r][0] = ps; sred[w][r][1] = pd; }
    }
    __syncthreads();
    // one thread per (r, h) combines partials across warps of that head
    constexpr int WPH = (KOUT / H) / 32;   // warps per head
    if (threadIdx.x < R * H) {
        int r = threadIdx.x / H, h = threadIdx.x - r * H;
        float ss = 0.0f, dd = 0.0f;
        #pragma unroll
        for (int ww = 0; ww < WPH; ww++) {
            ss += sred[h * WPH + ww][r][0];
            dd += sred[h * WPH + ww][r][1];
        }
        if (row0 + r < Nrows) {
            as_[(row0 + r) * H + h] = ss;
            ad_[(row0 + r) * H + h] = dd;
        }
    }
}

// ---------------- fused init: m=-inf, den=0, out=bias pattern ---------------
__global__ void k_init(float* __restrict__ m, float* __restrict__ den, int nm,
                       float* __restrict__ outbuf, const float* __restrict__ bias,
                       int bmask, int nout) {
    int i = blockIdx.x * blockDim.x + threadIdx.x;
    if (i < nm) { m[i] = -INFINITY; den[i] = 0.0f; }
    if (i < nout) outbuf[i] = __ldg(&bias[i & bmask]);
}

// ---------------- pass 1: per-edge logits + segment max ---------------------
template<int H>
__global__ void k_logit_max(const float* __restrict__ as_, const float* __restrict__ ad_,
                            float* __restrict__ m, float* __restrict__ eb, int Etot) {
    int e = blockIdx.x * blockDim.x + threadIdx.x;
    if (e >= Etot) return;
    int2 sd = g_sd[e];
    if (H == 4) {
        float4 a = *(const float4*)(as_ + sd.x * 4);
        float4 b = *(const float4*)(ad_ + sd.y * 4);
        float4 v = make_float4(lrelu(a.x + b.x), lrelu(a.y + b.y),
                               lrelu(a.z + b.z), lrelu(a.w + b.w));
        *(float4*)(eb + e * 4) = v;
        atomicMaxFloat(&m[sd.y * 4 + 0], v.x);
        atomicMaxFloat(&m[sd.y * 4 + 1], v.y);
        atomicMaxFloat(&m[sd.y * 4 + 2], v.z);
        atomicMaxFloat(&m[sd.y * 4 + 3], v.w);
    } else {
        float v = lrelu(as_[sd.x] + ad_[sd.y]);
        eb[e] = v;
        atomicMaxFloat(&m[sd.y], v);
    }
}

// ---------------- pass 2: p = exp(e - m[dst]); den[dst] += p ----------------
template<int H>
__global__ void k_exp_sum(const float* __restrict__ eb, const float* __restrict__ m,
                          float* __restrict__ den, float* __restrict__ pb, int Etot) {
    int e = blockIdx.x * blockDim.x + threadIdx.x;
    if (e >= Etot) return;
    int d = g_sd[e].y;
    if (H == 4) {
        float4 v = *(const float4*)(eb + e * 4);
        float4 mm = *(const float4*)(m + d * 4);
        float4 p = make_float4(__expf(v.x - mm.x), __expf(v.y - mm.y),
                               __expf(v.z - mm.z), __expf(v.w - mm.w));
        *(float4*)(pb + e * 4) = p;
        red_add_v4(den + d * 4, p);
    } else {
        float p = __expf(eb[e] - m[d]);
        pb[e] = p;
        atomicAdd(&den[d], p);
    }
}

// ---------------- pass 3: alpha = p * rcp(den[dst])  (in place on pb) -------
template<int H>
__global__ void k_alpha(const float* __restrict__ den, float* __restrict__ pb, int Etot) {
    int e = blockIdx.x * blockDim.x + threadIdx.x;
    if (e >= Etot) return;
    int d = g_sd[e].y;
    if (H == 4) {
        float4 p = *(const float4*)(pb + e * 4);
        float4 dn = *(const float4*)(den + d * 4);
        p.x *= __frcp_rn(dn.x); p.y *= __frcp_rn(dn.y);
        p.z *= __frcp_rn(dn.z); p.w *= __frcp_rn(dn.w);
        *(float4*)(pb + e * 4) = p;
    } else {
        pb[e] *= __frcp_rn(den[d]);
    }
}

// ---------------- pass 4: out[dst] += h[src] * alpha  (pure memory) ---------
// G = D/4 lanes per edge; each lane one float4 of channels. No MUFU here.
template<int H, int C>
__global__ void k_edge_agg(const float* __restrict__ Hm, const float* __restrict__ alpha,
                           float* __restrict__ out, int Etot) {
    constexpr int D = H * C;
    constexpr int G = D / 4;
    int t = blockIdx.x * blockDim.x + threadIdx.x;
    int e = t / G;
    if (e >= Etot) return;
    int g  = t - e * G;
    int ch = g * 4;
    int h  = ch / C;
    int2 sd = g_sd[e];
    float a = alpha[e * H + h];                       // broadcast within group
    float4 hv = *(const float4*)(Hm + sd.x * D + ch); // gather
    float4 o = make_float4(hv.x * a, hv.y * a, hv.z * a, hv.w * a);
    red_add_v4(out + sd.y * D + ch, o);
}

// ---------------- launcher -------------------------------------------------
static inline unsigned cdiv(long long a, long long b) { return (unsigned)((a + b - 1) / b); }

extern "C" void kernel_launch(void* const* d_in, const int* in_sizes, int n_in,
                              void* d_out, int out_size) {
    const float* x        = (const float*)d_in[0];
    const void*  ei       = d_in[1];
    const float* W1       = (const float*)d_in[2];
    const float* att_src1 = (const float*)d_in[3];
    const float* att_dst1 = (const float*)d_in[4];
    const float* b1       = (const float*)d_in[5];
    const float* W2       = (const float*)d_in[6];
    const float* att_src2 = (const float*)d_in[7];
    const float* att_dst2 = (const float*)d_in[8];
    const float* b2       = (const float*)d_in[9];
    float* out            = (float*)d_out;

    const int N    = in_sizes[0] / F1;
    const int E    = in_sizes[1] / 2;
    const int Etot = E + N;

    float *h1, *out1, *h2, *as1, *ad1, *m1, *den1, *as2, *ad2, *m2, *den2, *eb, *pb;
    cudaGetSymbolAddress((void**)&h1,   g_h1);
    cudaGetSymbolAddress((void**)&out1, g_out1);
    cudaGetSymbolAddress((void**)&h2,   g_h2);
    cudaGetSymbolAddress((void**)&as1,  g_as1);
    cudaGetSymbolAddress((void**)&ad1,  g_ad1);
    cudaGetSymbolAddress((void**)&m1,   g_m1);
    cudaGetSymbolAddress((void**)&den1, g_den1);
    cudaGetSymbolAddress((void**)&as2,  g_as2);
    cudaGetSymbolAddress((void**)&ad2,  g_ad2);
    cudaGetSymbolAddress((void**)&m2,   g_m2);
    cudaGetSymbolAddress((void**)&den2, g_den2);
    cudaGetSymbolAddress((void**)&eb,   g_e);
    cudaGetSymbolAddress((void**)&pb,   g_p);

    k_detect<<<1, 256>>>(ei, E, N);
    k_convert<<<cdiv(Etot, 256), 256>>>(ei, E, Etot, N);

    // ---- layer 1 ----
    k_gemm_att<F1, D1, H1, 4, false><<<cdiv(N, 4), D1>>>(x, W1, h1, att_src1, att_dst1, as1, ad1, N);
    k_init<<<cdiv((long long)N * D1, 256), 256>>>(m1, den1, N * H1, out1, b1, D1 - 1, N * D1);

    k_logit_max<H1><<<cdiv(Etot, 256), 256>>>(as1, ad1, m1, eb, Etot);
    k_exp_sum<H1><<<cdiv(Etot, 256), 256>>>(eb, m1, den1, pb, Etot);
    k_alpha<H1><<<cdiv(Etot, 256), 256>>>(den1, pb, Etot);
    k_edge_agg<H1, C1><<<cdiv((long long)Etot * (D1 / 4), 256), 256>>>(h1, pb, out1, Etot);

    // ---- layer 2 (ELU applied on A-load inside the GEMM) ----
    k_gemm_att<D1, D2, 1, 4, true><<<cdiv(N, 4), D2>>>(out1, W2, h2, att_src2, att_dst2, as2, ad2, N);
    k_init<<<cdiv((long long)N * D2, 256), 256>>>(m2, den2, N, out, b2, D2 - 1, N * D2);

    k_logit_max<1><<<cdiv(Etot, 256), 256>>>(as2, ad2, m2, eb, Etot);
    k_exp_sum<1><<<cdiv(Etot, 256), 256>>>(eb, m2, den2, pb, Etot);
    k_alpha<1><<<cdiv(Etot, 256), 256>>>(den2, pb, Etot);
    k_edge_agg<1, D2><<<cdiv((long long)Etot * (D2 / 4), 256), 256>>>(h2, pb, out, Etot);
}

// round 4
// speedup vs baseline: 1.3557x; 1.1556x over previous
#include <cuda_runtime.h>
#include <cuda_bf16.h>

// Problem dims (fixed by the dataset)
#define NMAX   50000
#define EMAX   800000
#define ETMAX  (NMAX + EMAX)      // edges + self loops
#define F1     128
#define H1     4
#define C1     32
#define D1     (H1 * C1)          // 128
#define D2     64
#define NEG_SLOPE 0.2f

// ---------------- scratch (static device globals; no allocation) -----------
static __device__ float g_h1  [NMAX * D1];    // x @ W1
static __device__ float g_out1[NMAX * D1];    // layer-1 aggregated (bias baked in)
static __device__ float g_h2  [NMAX * D2];    // elu(out1) @ W2
static __device__ float g_as1 [NMAX * H1];
static __device__ float g_ad1 [NMAX * H1];
static __device__ float g_den1[NMAX * H1];    // sum exp -> rcp
static __device__ float g_as2 [NMAX];
static __device__ float g_ad2 [NMAX];
static __device__ float g_den2[NMAX];
static __device__ float g_p   [ETMAX * H1];   // exp(e) per edge/head
static __device__ int2  g_sd  [ETMAX];        // (src, dst)
static __device__ int   g_flag[1];            // 1 => edge_index is int32

// ---------------- helpers --------------------------------------------------
__device__ __forceinline__ void red_add_v4(float* p, float4 v) {
    asm volatile("red.global.add.v4.f32 [%0], {%1,%2,%3,%4};"
                 :: "l"(p), "f"(v.x), "f"(v.y), "f"(v.z), "f"(v.w) : "memory");
}

__device__ __forceinline__ float lrelu(float v) {
    return v > 0.0f ? v : NEG_SLOPE * v;
}

__device__ __forceinline__ float warp_sum(float v) {
    #pragma unroll
    for (int o = 16; o > 0; o >>= 1) v += __shfl_xor_sync(0xFFFFFFFFu, v, o);
    return v;
}

// ---------------- dtype detection + edge conversion ------------------------
__global__ void k_detect(const void* ei, int E, int N) {
    if (threadIdx.x == 0) g_flag[0] = 0;
    __syncthreads();
    const long long* p = (const long long*)ei;
    int S = 2048;                       // 16KB read: in-bounds under both dtypes
    int bad = 0;
    for (int i = threadIdx.x; i < S; i += blockDim.x) {
        long long v = p[i];
        if (v < 0 || v >= (long long)N) bad = 1;
    }
    if (bad) atomicOr(&g_flag[0], 1);   // i64 interp invalid => data is int32
}

__global__ void k_convert(const void* ei, int E, int Etot, int N) {
    int i = blockIdx.x * blockDim.x + threadIdx.x;
    if (i >= Etot) return;
    int s, d;
    if (i < E) {
        if (g_flag[0]) {
            const int* p = (const int*)ei;
            s = p[i]; d = p[E + i];
        } else {
            const long long* p = (const long long*)ei;
            s = (int)p[i]; d = (int)p[E + i];
        }
    } else {
        s = d = i - E;                  // self loops
    }
    s = min(max(s, 0), N - 1);
    d = min(max(d, 0), N - 1);
    g_sd[i] = make_int2(s, d);
}

// ------- GEMM fused with attention logits (and optional ELU on A load) -----
// blockDim = KOUT; R rows per block; B hot in L1; 8 FFMA per B-load.
template<int K, int KOUT, int H, int R, bool ELU_IN>
__global__ void k_gemm_att(const float* __restrict__ A, const float* __restrict__ B,
                           float* __restrict__ C,
                           const float* __restrict__ att_s_w, const float* __restrict__ att_d_w,
                           float* __restrict__ as_, float* __restrict__ ad_, int Nrows) {
    constexpr int NW = KOUT / 32;
    __shared__ float sA[R][K];
    __shared__ float sred[NW][R][2];
    int row0 = blockIdx.x * R;
    int col  = threadIdx.x;
    int w    = col >> 5, lane = col & 31;

    for (int i = threadIdx.x; i < R * K; i += KOUT) {
        int r = i / K, k = i - r * K;
        float v = (row0 + r < Nrows) ? A[(row0 + r) * K + k] : 0.0f;
        if (ELU_IN) v = v > 0.0f ? v : expm1f(v);
        sA[r][k] = v;
    }
    __syncthreads();

    float acc[R];
    #pragma unroll
    for (int r = 0; r < R; r++) acc[r] = 0.0f;
    #pragma unroll 4
    for (int k = 0; k < K; k++) {
        float b = __ldg(&B[k * KOUT + col]);
        #pragma unroll
        for (int r = 0; r < R; r++) acc[r] += sA[r][k] * b;
    }

    float aw_s = __ldg(&att_s_w[col]);
    float aw_d = __ldg(&att_d_w[col]);
    #pragma unroll
    for (int r = 0; r < R; r++) {
        if (row0 + r < Nrows) C[(row0 + r) * KOUT + col] = acc[r];
        float ps = warp_sum(acc[r] * aw_s);
        float pd = warp_sum(acc[r] * aw_d);
        if (lane == 0) { sred[w][r][0] = ps; sred[w][r][1] = pd; }
    }
    __syncthreads();
    constexpr int WPH = (KOUT / H) / 32;   // warps per head
    if (threadIdx.x < R * H) {
        int r = threadIdx.x / H, h = threadIdx.x - r * H;
        float ss = 0.0f, dd = 0.0f;
        #pragma unroll
        for (int ww = 0; ww < WPH; ww++) {
            ss += sred[h * WPH + ww][r][0];
            dd += sred[h * WPH + ww][r][1];
        }
        if (row0 + r < Nrows) {
            as_[(row0 + r) * H + h] = ss;
            ad_[(row0 + r) * H + h] = dd;
        }
    }
}

// ---------------- vectorized init: den=0, out=bias pattern ------------------
// all counts are in float4 units
__global__ void k_init(float4* __restrict__ den, int nd4,
                       float4* __restrict__ outbuf, const float4* __restrict__ bias,
                       int bmask4, int nout4) {
    int i = blockIdx.x * blockDim.x + threadIdx.x;
    if (i < nd4) den[i] = make_float4(0.f, 0.f, 0.f, 0.f);
    if (i < nout4) outbuf[i] = __ldg(&bias[i & bmask4]);
}

// ------ edge pass: e = lrelu(as[s]+ad[d]); p = exp(e); den[d] += p ----------
template<int H>
__global__ void k_edge_exp(const float* __restrict__ as_, const float* __restrict__ ad_,
                           float* __restrict__ den, float* __restrict__ pb, int Etot) {
    int e = blockIdx.x * blockDim.x + threadIdx.x;
    if (e >= Etot) return;
    int2 sd = g_sd[e];
    if (H == 4) {
        float4 a = *(const float4*)(as_ + sd.x * 4);
        float4 b = *(const float4*)(ad_ + sd.y * 4);
        float4 p = make_float4(__expf(lrelu(a.x + b.x)), __expf(lrelu(a.y + b.y)),
                               __expf(lrelu(a.z + b.z)), __expf(lrelu(a.w + b.w)));
        *(float4*)(pb + e * 4) = p;
        red_add_v4(den + sd.y * 4, p);
    } else {
        float p = __expf(lrelu(as_[sd.x] + ad_[sd.y]));
        pb[e] = p;
        atomicAdd(&den[sd.y], p);
    }
}

// ---------------- den -> rcp(den) in place ---------------------------------
__global__ void k_rcp(float* __restrict__ den, int n) {
    int i = blockIdx.x * blockDim.x + threadIdx.x;
    if (i < n) den[i] = __frcp_rn(den[i]);
}

// ------ aggregation: out[dst] += h[src] * p[e] * den_rcp[dst] ---------------
template<int H, int C>
__global__ void k_edge_agg(const float* __restrict__ Hm, const float* __restrict__ pb,
                           const float* __restrict__ den_rcp,
                           float* __restrict__ out, int Etot) {
    constexpr int D = H * C;
    constexpr int G = D / 4;
    int t = blockIdx.x * blockDim.x + threadIdx.x;
    int e = t / G;
    if (e >= Etot) return;
    int g  = t - e * G;
    int ch = g * 4;
    int h  = ch / C;
    int2 sd = g_sd[e];
    float a = pb[e * H + h] * den_rcp[sd.y * H + h];
    float4 hv = *(const float4*)(Hm + sd.x * D + ch);
    float4 o = make_float4(hv.x * a, hv.y * a, hv.z * a, hv.w * a);
    red_add_v4(out + sd.y * D + ch, o);
}

// ---------------- launcher -------------------------------------------------
static inline unsigned cdiv(long long a, long long b) { return (unsigned)((a + b - 1) / b); }

extern "C" void kernel_launch(void* const* d_in, const int* in_sizes, int n_in,
                              void* d_out, int out_size) {
    const float* x        = (const float*)d_in[0];
    const void*  ei       = d_in[1];
    const float* W1       = (const float*)d_in[2];
    const float* att_src1 = (const float*)d_in[3];
    const float* att_dst1 = (const float*)d_in[4];
    const float* b1       = (const float*)d_in[5];
    const float* W2       = (const float*)d_in[6];
    const float* att_src2 = (const float*)d_in[7];
    const float* att_dst2 = (const float*)d_in[8];
    const float* b2       = (const float*)d_in[9];
    float* out            = (float*)d_out;

    const int N    = in_sizes[0] / F1;
    const int E    = in_sizes[1] / 2;
    const int Etot = E + N;

    float *h1, *out1, *h2, *as1, *ad1, *den1, *as2, *ad2, *den2, *pb;
    cudaGetSymbolAddress((void**)&h1,   g_h1);
    cudaGetSymbolAddress((void**)&out1, g_out1);
    cudaGetSymbolAddress((void**)&h2,   g_h2);
    cudaGetSymbolAddress((void**)&as1,  g_as1);
    cudaGetSymbolAddress((void**)&ad1,  g_ad1);
    cudaGetSymbolAddress((void**)&den1, g_den1);
    cudaGetSymbolAddress((void**)&as2,  g_as2);
    cudaGetSymbolAddress((void**)&ad2,  g_ad2);
    cudaGetSymbolAddress((void**)&den2, g_den2);
    cudaGetSymbolAddress((void**)&pb,   g_p);

    k_detect<<<1, 256>>>(ei, E, N);
    k_convert<<<cdiv(Etot, 256), 256>>>(ei, E, Etot, N);

    // ---- layer 1 ----
    k_gemm_att<F1, D1, H1, 8, false><<<cdiv(N, 8), D1>>>(x, W1, h1, att_src1, att_dst1, as1, ad1, N);
    k_init<<<cdiv((long long)N * D1 / 4, 256), 256>>>((float4*)den1, N * H1 / 4,
                                                      (float4*)out1, (const float4*)b1,
                                                      D1 / 4 - 1, N * D1 / 4);
    k_edge_exp<H1><<<cdiv(Etot, 256), 256>>>(as1, ad1, den1, pb, Etot);
    k_rcp<<<cdiv(N * H1, 256), 256>>>(den1, N * H1);
    k_edge_agg<H1, C1><<<cdiv((long long)Etot * (D1 / 4), 256), 256>>>(h1, pb, den1, out1, Etot);

    // ---- layer 2 (ELU applied on A-load inside the GEMM) ----
    k_gemm_att<D1, D2, 1, 8, true><<<cdiv(N, 8), D2>>>(out1, W2, h2, att_src2, att_dst2, as2, ad2, N);
    k_init<<<cdiv((long long)N * D2 / 4, 256), 256>>>((float4*)den2, N / 4,
                                                      (float4*)out, (const float4*)b2,
                                                      D2 / 4 - 1, N * D2 / 4);
    k_edge_exp<1><<<cdiv(Etot, 256), 256>>>(as2, ad2, den2, pb, Etot);
    k_rcp<<<cdiv(N, 256), 256>>>(den2, N);
    k_edge_agg<1, D2><<<cdiv((long long)Etot * (D2 / 4), 256), 256>>>(h2, pb, den2, out, Etot);
}

// round 5
// speedup vs baseline: 1.4276x; 1.0530x over previous
#include <cuda_runtime.h>
#include <cuda_bf16.h>

// Problem dims (fixed by the dataset)
#define NMAX   50000
#define EMAX   800000
#define ETMAX  (NMAX + EMAX)      // edges + self loops
#define F1     128
#define H1     4
#define C1     32
#define D1     (H1 * C1)          // 128
#define D2     64
#define NEG_SLOPE 0.2f

// ---------------- scratch (static device globals; no allocation) -----------
static __device__ float g_h1  [NMAX * D1];    // x @ W1
static __device__ float g_out1[NMAX * D1];    // layer-1 output (bias baked in)
static __device__ float g_h2  [NMAX * D2];    // elu(out1) @ W2
static __device__ float g_as1 [NMAX * H1];
static __device__ float g_ad1 [NMAX * H1];
static __device__ float g_as2 [NMAX];
static __device__ float g_ad2 [NMAX];
static __device__ int   g_cnt [NMAX];         // in-degree histogram
static __device__ int   g_row [NMAX + 1];     // CSR row pointers (by dst)
static __device__ int   g_wp  [NMAX];         // scatter write cursors
static __device__ int   g_csrc[ETMAX];        // CSR: src node per slot
static __device__ int2  g_sd  [ETMAX];        // raw (src, dst)
static __device__ int   g_flag[1];            // 1 => edge_index is int32

// ---------------- helpers --------------------------------------------------
__device__ __forceinline__ float warp_sum(float v) {
    #pragma unroll
    for (int o = 16; o > 0; o >>= 1) v += __shfl_xor_sync(0xFFFFFFFFu, v, o);
    return v;
}

// ---------------- dtype detection ------------------------------------------
__global__ void k_detect(const void* ei, int E, int N) {
    if (threadIdx.x == 0) g_flag[0] = 0;
    __syncthreads();
    const long long* p = (const long long*)ei;
    int S = 2048;                       // 16KB read: in-bounds under both dtypes
    int bad = 0;
    for (int i = threadIdx.x; i < S; i += blockDim.x) {
        long long v = p[i];
        if (v < 0 || v >= (long long)N) bad = 1;
    }
    if (bad) atomicOr(&g_flag[0], 1);   // i64 interp invalid => data is int32
}

__global__ void k_zero_cnt(int N) {
    int i = blockIdx.x * blockDim.x + threadIdx.x;
    if (i < N) g_cnt[i] = 0;
}

// convert + histogram of dst (fused)
__global__ void k_convert(const void* ei, int E, int Etot, int N) {
    int i = blockIdx.x * blockDim.x + threadIdx.x;
    if (i >= Etot) return;
    int s, d;
    if (i < E) {
        if (g_flag[0]) {
            const int* p = (const int*)ei;
            s = p[i]; d = p[E + i];
        } else {
            const long long* p = (const long long*)ei;
            s = (int)p[i]; d = (int)p[E + i];
        }
    } else {
        s = d = i - E;                  // self loops
    }
    s = min(max(s, 0), N - 1);
    d = min(max(d, 0), N - 1);
    g_sd[i] = make_int2(s, d);
    atomicAdd(&g_cnt[d], 1);
}

// single-block exclusive scan of g_cnt -> g_row, g_wp; g_row[N] = total
__global__ void k_scan(int N) {
    __shared__ int ssum[1024];
    int t = threadIdx.x;
    int chunk = (N + 1023) / 1024;
    int base = t * chunk;
    int s = 0;
    for (int i = 0; i < chunk; i++) {
        int idx = base + i;
        if (idx < N) s += g_cnt[idx];
    }
    ssum[t] = s;
    __syncthreads();
    for (int off = 1; off < 1024; off <<= 1) {
        int v = (t >= off) ? ssum[t - off] : 0;
        __syncthreads();
        ssum[t] += v;
        __syncthreads();
    }
    int run = (t == 0) ? 0 : ssum[t - 1];
    for (int i = 0; i < chunk; i++) {
        int idx = base + i;
        if (idx < N) {
            g_row[idx] = run;
            g_wp[idx]  = run;
            run += g_cnt[idx];
        }
    }
    if (t == 1023) g_row[N] = ssum[1023];
}

// scatter edges into dst-sorted CSR
__global__ void k_scatter(int Etot) {
    int i = blockIdx.x * blockDim.x + threadIdx.x;
    if (i >= Etot) return;
    int2 sd = g_sd[i];
    int pos = atomicAdd(&g_wp[sd.y], 1);
    g_csrc[pos] = sd.x;
}

// ------- GEMM fused with attention logits (and optional ELU on A load) -----
template<int K, int KOUT, int H, int R, bool ELU_IN>
__global__ void k_gemm_att(const float* __restrict__ A, const float* __restrict__ B,
                           float* __restrict__ C,
                           const float* __restrict__ att_s_w, const float* __restrict__ att_d_w,
                           float* __restrict__ as_, float* __restrict__ ad_, int Nrows) {
    constexpr int NW = KOUT / 32;
    __shared__ float sA[R][K];
    __shared__ float sred[NW][R][2];
    int row0 = blockIdx.x * R;
    int col  = threadIdx.x;
    int w    = col >> 5, lane = col & 31;

    for (int i = threadIdx.x; i < R * K; i += KOUT) {
        int r = i / K, k = i - r * K;
        float v = (row0 + r < Nrows) ? A[(row0 + r) * K + k] : 0.0f;
        if (ELU_IN) v = v > 0.0f ? v : expm1f(v);
        sA[r][k] = v;
    }
    __syncthreads();

    float acc[R];
    #pragma unroll
    for (int r = 0; r < R; r++) acc[r] = 0.0f;
    #pragma unroll 4
    for (int k = 0; k < K; k++) {
        float b = __ldg(&B[k * KOUT + col]);
        #pragma unroll
        for (int r = 0; r < R; r++) acc[r] += sA[r][k] * b;
    }

    float aw_s = __ldg(&att_s_w[col]);
    float aw_d = __ldg(&att_d_w[col]);
    #pragma unroll
    for (int r = 0; r < R; r++) {
        if (row0 + r < Nrows) C[(row0 + r) * KOUT + col] = acc[r];
        float ps = warp_sum(acc[r] * aw_s);
        float pd = warp_sum(acc[r] * aw_d);
        if (lane == 0) { sred[w][r][0] = ps; sred[w][r][1] = pd; }
    }
    __syncthreads();
    constexpr int WPH = (KOUT / H) / 32;   // warps per head
    if (threadIdx.x < R * H) {
        int r = threadIdx.x / H, h = threadIdx.x - r * H;
        float ss = 0.0f, dd = 0.0f;
        #pragma unroll
        for (int ww = 0; ww < WPH; ww++) {
            ss += sred[h * WPH + ww][r][0];
            dd += sred[h * WPH + ww][r][1];
        }
        if (row0 + r < Nrows) {
            as_[(row0 + r) * H + h] = ss;
            ad_[(row0 + r) * H + h] = dd;
        }
    }
}

// ---- fused softmax + aggregation: warp per destination node ----------------
// out[n] = (sum_e p_e * h[src_e]) * rcp(sum_e p_e) + bias
// p_e = exp(lrelu(as[src_e] + ad[n])), computed in-loop (1 MUFU instr / edge).
template<int H, int C>
__global__ void k_agg(const float* __restrict__ Hm,
                      const float* __restrict__ as_, const float* __restrict__ ad_,
                      const float* __restrict__ bias,
                      float* __restrict__ out, int N) {
    constexpr int D = H * C;
    constexpr int V = D / 32;            // floats per lane (4 or 2)
    int warp = (blockIdx.x * blockDim.x + threadIdx.x) >> 5;
    if (warp >= N) return;
    int lane = threadIdx.x & 31;
    int h = (lane * V) / C;              // head owned by this lane
    float adv = ad_[warp * H + h];
    int beg = __ldg(&g_row[warp]), end = __ldg(&g_row[warp + 1]);

    float acc[V];
    #pragma unroll
    for (int v = 0; v < V; v++) acc[v] = 0.0f;
    float den = 0.0f;

    for (int pos = beg; pos < end; pos++) {
        int s = __ldg(&g_csrc[pos]);                 // broadcast
        float e = as_[s * H + h] + adv;
        e = e > 0.0f ? e : NEG_SLOPE * e;
        float p = __expf(e);
        den += p;
        if (V == 4) {
            float4 hv = *(const float4*)(Hm + s * D + lane * 4);
            acc[0] += hv.x * p; acc[1] += hv.y * p;
            acc[2] += hv.z * p; acc[3] += hv.w * p;
        } else {
            float2 hv = *(const float2*)(Hm + s * D + lane * 2);
            acc[0] += hv.x * p; acc[1] += hv.y * p;
        }
    }
    float r = __frcp_rn(den);
    if (V == 4) {
        float4 b = *(const float4*)(bias + lane * 4);
        float4 o = make_float4(acc[0] * r + b.x, acc[1] * r + b.y,
                               acc[2] * r + b.z, acc[3] * r + b.w);
        *(float4*)(out + warp * D + lane * 4) = o;
    } else {
        float2 b = *(const float2*)(bias + lane * 2);
        float2 o = make_float2(acc[0] * r + b.x, acc[1] * r + b.y);
        *(float2*)(out + warp * D + lane * 2) = o;
    }
}

// ---------------- launcher -------------------------------------------------
static inline unsigned cdiv(long long a, long long b) { return (unsigned)((a + b - 1) / b); }

extern "C" void kernel_launch(void* const* d_in, const int* in_sizes, int n_in,
                              void* d_out, int out_size) {
    const float* x        = (const float*)d_in[0];
    const void*  ei       = d_in[1];
    const float* W1       = (const float*)d_in[2];
    const float* att_src1 = (const float*)d_in[3];
    const float* att_dst1 = (const float*)d_in[4];
    const float* b1       = (const float*)d_in[5];
    const float* W2       = (const float*)d_in[6];
    const float* att_src2 = (const float*)d_in[7];
    const float* att_dst2 = (const float*)d_in[8];
    const float* b2       = (const float*)d_in[9];
    float* out            = (float*)d_out;

    const int N    = in_sizes[0] / F1;
    const int E    = in_sizes[1] / 2;
    const int Etot = E + N;

    float *h1, *out1, *h2, *as1, *ad1, *as2, *ad2;
    cudaGetSymbolAddress((void**)&h1,   g_h1);
    cudaGetSymbolAddress((void**)&out1, g_out1);
    cudaGetSymbolAddress((void**)&h2,   g_h2);
    cudaGetSymbolAddress((void**)&as1,  g_as1);
    cudaGetSymbolAddress((void**)&ad1,  g_ad1);
    cudaGetSymbolAddress((void**)&as2,  g_as2);
    cudaGetSymbolAddress((void**)&ad2,  g_ad2);

    // ---- CSR build (shared by both layers) ----
    k_detect<<<1, 256>>>(ei, E, N);
    k_zero_cnt<<<cdiv(N, 256), 256>>>(N);
    k_convert<<<cdiv(Etot, 256), 256>>>(ei, E, Etot, N);
    k_scan<<<1, 1024>>>(N);
    k_scatter<<<cdiv(Etot, 256), 256>>>(Etot);

    // ---- layer 1 ----
    k_gemm_att<F1, D1, H1, 8, false><<<cdiv(N, 8), D1>>>(x, W1, h1, att_src1, att_dst1, as1, ad1, N);
    k_agg<H1, C1><<<cdiv((long long)N * 32, 256), 256>>>(h1, as1, ad1, b1, out1, N);

    // ---- layer 2 (ELU applied on A-load inside the GEMM) ----
    k_gemm_att<D1, D2, 1, 8, true><<<cdiv(N, 8), D2>>>(out1, W2, h2, att_src2, att_dst2, as2, ad2, N);
    k_agg<1, D2><<<cdiv((long long)N * 32, 256), 256>>>(h2, as2, ad2, b2, out, N);
}

// round 6
// speedup vs baseline: 1.8745x; 1.3130x over previous
#include <cuda_runtime.h>
#include <cuda_bf16.h>

// Problem dims (fixed by the dataset)
#define NMAX   50000
#define EMAX   800000
#define ETMAX  (NMAX + EMAX)      // edges + self loops
#define F1     128
#define H1     4
#define C1     32
#define D1     (H1 * C1)          // 128
#define D2     64
#define NEG_SLOPE 0.2f
#define SCAN_T 1024
#define SCAN_NB ((NMAX + SCAN_T - 1) / SCAN_T)   // 49

// ---------------- scratch (static device globals; no allocation) -----------
static __device__ float g_h1  [NMAX * D1];    // x @ W1
static __device__ float g_out1[NMAX * D1];    // layer-1 output (bias baked in)
static __device__ float g_h2  [NMAX * D2];    // elu(out1) @ W2
static __device__ float g_as1 [NMAX * H1];
static __device__ float g_ad1 [NMAX * H1];
static __device__ float g_as2 [NMAX];
static __device__ float g_ad2 [NMAX];
static __device__ int   g_cnt [NMAX];         // in-degree histogram
static __device__ int   g_row [NMAX + 1];     // CSR row pointers (by dst)
static __device__ int   g_wp  [NMAX];         // scatter write cursors
static __device__ int   g_csrc[ETMAX];        // CSR: src node per slot
static __device__ int2  g_sd  [ETMAX];        // raw (src, dst)
static __device__ int   g_bsum[SCAN_NB];      // per-block sums
static __device__ int   g_boff[SCAN_NB];      // per-block exclusive offsets
static __device__ int   g_flag[1];            // 1 => edge_index is int32

// ---------------- helpers --------------------------------------------------
__device__ __forceinline__ float warp_sum(float v) {
    #pragma unroll
    for (int o = 16; o > 0; o >>= 1) v += __shfl_xor_sync(0xFFFFFFFFu, v, o);
    return v;
}

// ---------------- dtype detection ------------------------------------------
__global__ void k_detect(const void* ei, int E, int N) {
    if (threadIdx.x == 0) g_flag[0] = 0;
    __syncthreads();
    const long long* p = (const long long*)ei;
    int S = 2048;                       // 16KB read: in-bounds under both dtypes
    int bad = 0;
    for (int i = threadIdx.x; i < S; i += blockDim.x) {
        long long v = p[i];
        if (v < 0 || v >= (long long)N) bad = 1;
    }
    if (bad) atomicOr(&g_flag[0], 1);   // i64 interp invalid => data is int32
}

__global__ void k_zero_cnt(int N) {
    int i = blockIdx.x * blockDim.x + threadIdx.x;
    if (i < N) g_cnt[i] = 0;
}

// convert + histogram of dst (fused)
__global__ void k_convert(const void* ei, int E, int Etot, int N) {
    int i = blockIdx.x * blockDim.x + threadIdx.x;
    if (i >= Etot) return;
    int s, d;
    if (i < E) {
        if (g_flag[0]) {
            const int* p = (const int*)ei;
            s = p[i]; d = p[E + i];
        } else {
            const long long* p = (const long long*)ei;
            s = (int)p[i]; d = (int)p[E + i];
        }
    } else {
        s = d = i - E;                  // self loops
    }
    s = min(max(s, 0), N - 1);
    d = min(max(d, 0), N - 1);
    g_sd[i] = make_int2(s, d);
    atomicAdd(&g_cnt[d], 1);
}

// ---------------- 3-phase exclusive scan of g_cnt -> g_row -----------------
// phase 1: block-local exclusive scan (1 elem/thread) + per-block sums
__global__ void k_scan1(int N) {
    __shared__ int sh[SCAN_T];
    int i = blockIdx.x * SCAN_T + threadIdx.x;
    int v = (i < N) ? g_cnt[i] : 0;
    sh[threadIdx.x] = v;
    __syncthreads();
    #pragma unroll
    for (int off = 1; off < SCAN_T; off <<= 1) {
        int t = (threadIdx.x >= off) ? sh[threadIdx.x - off] : 0;
        __syncthreads();
        sh[threadIdx.x] += t;
        __syncthreads();
    }
    if (i < N) g_row[i] = sh[threadIdx.x] - v;   // block-local exclusive
    if (threadIdx.x == SCAN_T - 1) g_bsum[blockIdx.x] = sh[SCAN_T - 1];
}

// phase 2: one warp scans the block sums (SCAN_NB <= 64)
__global__ void k_scan2(int nb) {
    int t = threadIdx.x;
    int v = (t < nb) ? g_bsum[t] : 0;
    int orig = v;
    #pragma unroll
    for (int off = 1; off < 64; off <<= 1) {
        int u = __shfl_up_sync(0xFFFFFFFFu, v, off);  // within-warp only
        if ((t & 31) >= off) v += u;
    }
    // handle two warps (64 threads): warp1 adds total of warp0
    __shared__ int w0tot;
    if (t == 31) w0tot = v;
    __syncthreads();
    if (t >= 32) v += w0tot;
    if (t < nb) g_boff[t] = v - orig;   // exclusive
}

// phase 3: add block offsets, fill write cursors, close the row array
__global__ void k_scan3(int N, int Etot) {
    int i = blockIdx.x * blockDim.x + threadIdx.x;
    if (i < N) {
        int r = g_row[i] + g_boff[i / SCAN_T];
        g_row[i] = r;
        g_wp[i]  = r;
    }
    if (i == 0) g_row[N] = Etot;
}

// scatter edges into dst-sorted CSR
__global__ void k_scatter(int Etot) {
    int i = blockIdx.x * blockDim.x + threadIdx.x;
    if (i >= Etot) return;
    int2 sd = g_sd[i];
    int pos = atomicAdd(&g_wp[sd.y], 1);
    g_csrc[pos] = sd.x;
}

// ------- GEMM fused with attention logits (and optional ELU on A load) -----
template<int K, int KOUT, int H, int R, bool ELU_IN>
__global__ void k_gemm_att(const float* __restrict__ A, const float* __restrict__ B,
                           float* __restrict__ C,
                           const float* __restrict__ att_s_w, const float* __restrict__ att_d_w,
                           float* __restrict__ as_, float* __restrict__ ad_, int Nrows) {
    constexpr int NW = KOUT / 32;
    __shared__ float sA[R][K];
    __shared__ float sred[NW][R][2];
    int row0 = blockIdx.x * R;
    int col  = threadIdx.x;
    int w    = col >> 5, lane = col & 31;

    for (int i = threadIdx.x; i < R * K; i += KOUT) {
        int r = i / K, k = i - r * K;
        float v = (row0 + r < Nrows) ? A[(row0 + r) * K + k] : 0.0f;
        if (ELU_IN) v = v > 0.0f ? v : expm1f(v);
        sA[r][k] = v;
    }
    __syncthreads();

    float acc[R];
    #pragma unroll
    for (int r = 0; r < R; r++) acc[r] = 0.0f;
    #pragma unroll 4
    for (int k = 0; k < K; k++) {
        float b = __ldg(&B[k * KOUT + col]);
        #pragma unroll
        for (int r = 0; r < R; r++) acc[r] += sA[r][k] * b;
    }

    float aw_s = __ldg(&att_s_w[col]);
    float aw_d = __ldg(&att_d_w[col]);
    #pragma unroll
    for (int r = 0; r < R; r++) {
        if (row0 + r < Nrows) C[(row0 + r) * KOUT + col] = acc[r];
        float ps = warp_sum(acc[r] * aw_s);
        float pd = warp_sum(acc[r] * aw_d);
        if (lane == 0) { sred[w][r][0] = ps; sred[w][r][1] = pd; }
    }
    __syncthreads();
    constexpr int WPH = (KOUT / H) / 32;   // warps per head
    if (threadIdx.x < R * H) {
        int r = threadIdx.x / H, h = threadIdx.x - r * H;
        float ss = 0.0f, dd = 0.0f;
        #pragma unroll
        for (int ww = 0; ww < WPH; ww++) {
            ss += sred[h * WPH + ww][r][0];
            dd += sred[h * WPH + ww][r][1];
        }
        if (row0 + r < Nrows) {
            as_[(row0 + r) * H + h] = ss;
            ad_[(row0 + r) * H + h] = dd;
        }
    }
}

// ---- fused softmax + aggregation: warp per destination node ----------------
// out[n] = (sum_e p_e * h[src_e]) * rcp(sum_e p_e) + bias
template<int H, int C>
__global__ void k_agg(const float* __restrict__ Hm,
                      const float* __restrict__ as_, const float* __restrict__ ad_,
                      const float* __restrict__ bias,
                      float* __restrict__ out, int N) {
    constexpr int D = H * C;
    constexpr int V = D / 32;            // floats per lane (4 or 2)
    int warp = (blockIdx.x * blockDim.x + threadIdx.x) >> 5;
    if (warp >= N) return;
    int lane = threadIdx.x & 31;
    int h = (lane * V) / C;              // head owned by this lane
    float adv = ad_[warp * H + h];
    int beg = __ldg(&g_row[warp]), end = __ldg(&g_row[warp + 1]);

    float acc[V];
    #pragma unroll
    for (int v = 0; v < V; v++) acc[v] = 0.0f;
    float den = 0.0f;

    for (int pos = beg; pos < end; pos++) {
        int s = __ldg(&g_csrc[pos]);                 // broadcast
        float e = as_[s * H + h] + adv;
        e = e > 0.0f ? e : NEG_SLOPE * e;
        float p = __expf(e);
        den += p;
        if (V == 4) {
            float4 hv = *(const float4*)(Hm + s * D + lane * 4);
            acc[0] += hv.x * p; acc[1] += hv.y * p;
            acc[2] += hv.z * p; acc[3] += hv.w * p;
        } else {
            float2 hv = *(const float2*)(Hm + s * D + lane * 2);
            acc[0] += hv.x * p; acc[1] += hv.y * p;
        }
    }
    float r = __frcp_rn(den);
    if (V == 4) {
        float4 b = *(const float4*)(bias + lane * 4);
        float4 o = make_float4(acc[0] * r + b.x, acc[1] * r + b.y,
                               acc[2] * r + b.z, acc[3] * r + b.w);
        *(float4*)(out + warp * D + lane * 4) = o;
    } else {
        float2 b = *(const float2*)(bias + lane * 2);
        float2 o = make_float2(acc[0] * r + b.x, acc[1] * r + b.y);
        *(float2*)(out + warp * D + lane * 2) = o;
    }
}

// ---------------- launcher -------------------------------------------------
static inline unsigned cdiv(long long a, long long b) { return (unsigned)((a + b - 1) / b); }

extern "C" void kernel_launch(void* const* d_in, const int* in_sizes, int n_in,
                              void* d_out, int out_size) {
    const float* x        = (const float*)d_in[0];
    const void*  ei       = d_in[1];
    const float* W1       = (const float*)d_in[2];
    const float* att_src1 = (const float*)d_in[3];
    const float* att_dst1 = (const float*)d_in[4];
    const float* b1       = (const float*)d_in[5];
    const float* W2       = (const float*)d_in[6];
    const float* att_src2 = (const float*)d_in[7];
    const float* att_dst2 = (const float*)d_in[8];
    const float* b2       = (const float*)d_in[9];
    float* out            = (float*)d_out;

    const int N    = in_sizes[0] / F1;
    const int E    = in_sizes[1] / 2;
    const int Etot = E + N;
    const int nb   = (N + SCAN_T - 1) / SCAN_T;

    float *h1, *out1, *h2, *as1, *ad1, *as2, *ad2;
    cudaGetSymbolAddress((void**)&h1,   g_h1);
    cudaGetSymbolAddress((void**)&out1, g_out1);
    cudaGetSymbolAddress((void**)&h2,   g_h2);
    cudaGetSymbolAddress((void**)&as1,  g_as1);
    cudaGetSymbolAddress((void**)&ad1,  g_ad1);
    cudaGetSymbolAddress((void**)&as2,  g_as2);
    cudaGetSymbolAddress((void**)&ad2,  g_ad2);

    // ---- CSR build (shared by both layers) ----
    k_detect<<<1, 256>>>(ei, E, N);
    k_zero_cnt<<<cdiv(N, 256), 256>>>(N);
    k_convert<<<cdiv(Etot, 256), 256>>>(ei, E, Etot, N);
    k_scan1<<<nb, SCAN_T>>>(N);
    k_scan2<<<1, 64>>>(nb);
    k_scan3<<<cdiv(N, 256), 256>>>(N, Etot);
    k_scatter<<<cdiv(Etot, 256), 256>>>(Etot);

    // ---- layer 1 ----
    k_gemm_att<F1, D1, H1, 8, false><<<cdiv(N, 8), D1>>>(x, W1, h1, att_src1, att_dst1, as1, ad1, N);
    k_agg<H1, C1><<<cdiv((long long)N * 32, 256), 256>>>(h1, as1, ad1, b1, out1, N);

    // ---- layer 2 (ELU applied on A-load inside the GEMM) ----
    k_gemm_att<D1, D2, 1, 8, true><<<cdiv(N, 8), D2>>>(out1, W2, h2, att_src2, att_dst2, as2, ad2, N);
    k_agg<1, D2><<<cdiv((long long)N * 32, 256), 256>>>(h2, as2, ad2, b2, out, N);
}